// round 3
// baseline (speedup 1.0000x reference)
#include <cuda_runtime.h>
#include <cstdint>

// Problem constants
#define B_   256
#define T_   256
#define C_   384
#define NH_  8
#define HD_  48

// Scratch (static __device__ arrays — no allocation APIs allowed)
__device__ float g_q[B_ * NH_ * T_ * HD_];    // [B, NH, T, HD]
__device__ float g_k[B_ * NH_ * T_ * HD_];
__device__ float g_v[B_ * NH_ * T_ * HD_];
__device__ float g_att[B_ * T_ * C_];         // attention output, [B*T, C]

// ---------------------------------------------------------------------------
// tf32 helpers
// ---------------------------------------------------------------------------
__device__ __forceinline__ uint32_t f2tf32(float x) {
    uint32_t r;
    asm("cvt.rna.tf32.f32 %0, %1;" : "=r"(r) : "f"(x));
    return r;
}

__device__ __forceinline__ uint2 split_tf32(float f) {
    uint2 r;
    r.x = f2tf32(f);
    r.y = f2tf32(f - __uint_as_float(r.x));
    return r;
}

__device__ __forceinline__ void mma_tf32(float c[4], const uint32_t a[4], const uint32_t b[2]) {
    asm volatile(
        "mma.sync.aligned.m16n8k8.row.col.f32.tf32.tf32.f32 "
        "{%0,%1,%2,%3}, {%4,%5,%6,%7}, {%8,%9}, {%0,%1,%2,%3};\n"
        : "+f"(c[0]), "+f"(c[1]), "+f"(c[2]), "+f"(c[3])
        : "r"(a[0]), "r"(a[1]), "r"(a[2]), "r"(a[3]),
          "r"(b[0]), "r"(b[1]));
}

// ---------------------------------------------------------------------------
// Tensor-core GEMM (3xTF32 compensated, hi/lo pre-split in smem, double-buffered)
//   C[n,o] = sum_k A[n,k]*W[o,k] + bias[o]
// Block tile 128(M) x 64(N), BK=16, 256 threads = 8 warps, warp tile 32x32.
// smem: packed uint2{hi,lo} per element, row stride 20 uint2 (conflict-free).
// MODE 0: QKV epilogue — scatter into g_q/g_k/g_v head-major.
// MODE 1: proj epilogue — A := g_att, linear store + bias.
// ---------------------------------------------------------------------------
#define BM 128
#define BN 64
#define BK 16
#define RS 20                     // smem row stride in uint2 (BK + 4 pad)
#define NSLAB (C_ / BK)           // 24
#define SMEM_U2 (2 * BM * RS + 2 * BN * RS)   // 7680 uint2 = 61440 bytes

template <int MODE>
__global__ __launch_bounds__(256) void tgemm_kernel(
    const float* __restrict__ A,
    const float* __restrict__ W,
    const float* __restrict__ bias,
    float* __restrict__ out)
{
    const int K = C_;  // 384

    extern __shared__ uint2 sm[];
    uint2* Asm = sm;                  // [2][BM][RS]
    uint2* Wsm = sm + 2 * BM * RS;    // [2][BN][RS]

#define AS(b, r, k) Asm[((b) * BM + (r)) * RS + (k)]
#define WS(b, r, k) Wsm[((b) * BN + (r)) * RS + (k)]

    const int tid  = threadIdx.x;
    const int wid  = tid >> 5;
    const int lane = tid & 31;
    const int gid  = lane >> 2;   // 0..7
    const int tig  = lane & 3;    // 0..3

    const int warpM = wid & 3;    // 0..3  -> 4*32 = 128 rows
    const int warpN = wid >> 2;   // 0..1  -> 2*32 = 64 cols

    const int n0 = blockIdx.x * BM;
    const int o0 = blockIdx.y * BN;

    const float* Ap = (MODE == 1) ? (const float*)g_att : A;

    float acc[2][4][4];
#pragma unroll
    for (int mi = 0; mi < 2; ++mi)
#pragma unroll
        for (int ni = 0; ni < 4; ++ni)
#pragma unroll
            for (int c = 0; c < 4; ++c) acc[mi][ni][c] = 0.f;

    // gmem->smem load mapping (per BK=16 slab):
    // A tile: 128 rows x 16 cols = 512 float4; thread does 2
    // W tile:  64 rows x 16 cols = 256 float4; thread does 1
    const int am0 = tid >> 1;
    const int ak0 = (tid & 1) ? 4 : 0;    // 2*tid   -> k 0 or 8
    const int ak0k = ((2 * tid) & 3) * 4; // 0 or 8
    const int am1 = (2 * tid + 1) >> 2;
    const int ak1k = ((2 * tid + 1) & 3) * 4; // 4 or 12
    (void)ak0;

    const float* aptr0 = Ap + (size_t)(n0 + am0) * K + ak0k;
    const float* aptr1 = Ap + (size_t)(n0 + am1) * K + ak1k;
    const int wm = tid >> 2;
    const int wk = (tid & 3) * 4;
    const float* wptr = W + (size_t)(o0 + wm) * K + wk;

    // ---- prologue: load + split-store slab 0 into buffer 0
    float4 ra0 = *(const float4*)(aptr0);
    float4 ra1 = *(const float4*)(aptr1);
    float4 rw0 = *(const float4*)(wptr);

    AS(0, am0, ak0k + 0) = split_tf32(ra0.x);
    AS(0, am0, ak0k + 1) = split_tf32(ra0.y);
    AS(0, am0, ak0k + 2) = split_tf32(ra0.z);
    AS(0, am0, ak0k + 3) = split_tf32(ra0.w);
    AS(0, am1, ak1k + 0) = split_tf32(ra1.x);
    AS(0, am1, ak1k + 1) = split_tf32(ra1.y);
    AS(0, am1, ak1k + 2) = split_tf32(ra1.z);
    AS(0, am1, ak1k + 3) = split_tf32(ra1.w);
    WS(0, wm, wk + 0) = split_tf32(rw0.x);
    WS(0, wm, wk + 1) = split_tf32(rw0.y);
    WS(0, wm, wk + 2) = split_tf32(rw0.z);
    WS(0, wm, wk + 3) = split_tf32(rw0.w);
    __syncthreads();

    for (int s = 0; s < NSLAB; ++s) {
        const int buf = s & 1;

        // prefetch next slab to registers
        if (s + 1 < NSLAB) {
            const int k0 = (s + 1) * BK;
            ra0 = *(const float4*)(aptr0 + k0);
            ra1 = *(const float4*)(aptr1 + k0);
            rw0 = *(const float4*)(wptr + k0);
        }

        // compute on current buffer
#pragma unroll
        for (int kk = 0; kk < BK; kk += 8) {
            uint32_t Ah[2][4], Al[2][4];
#pragma unroll
            for (int mi = 0; mi < 2; ++mi) {
                const int r0 = warpM * 32 + mi * 16 + gid;
                const int r1 = r0 + 8;
                const uint2 q0 = AS(buf, r0, kk + tig);
                const uint2 q1 = AS(buf, r1, kk + tig);
                const uint2 q2 = AS(buf, r0, kk + tig + 4);
                const uint2 q3 = AS(buf, r1, kk + tig + 4);
                Ah[mi][0] = q0.x; Al[mi][0] = q0.y;
                Ah[mi][1] = q1.x; Al[mi][1] = q1.y;
                Ah[mi][2] = q2.x; Al[mi][2] = q2.y;
                Ah[mi][3] = q3.x; Al[mi][3] = q3.y;
            }
            uint32_t Bh[4][2], Bl[4][2];
#pragma unroll
            for (int ni = 0; ni < 4; ++ni) {
                const int r = warpN * 32 + ni * 8 + gid;
                const uint2 q0 = WS(buf, r, kk + tig);
                const uint2 q1 = WS(buf, r, kk + tig + 4);
                Bh[ni][0] = q0.x; Bl[ni][0] = q0.y;
                Bh[ni][1] = q1.x; Bl[ni][1] = q1.y;
            }
#pragma unroll
            for (int mi = 0; mi < 2; ++mi)
#pragma unroll
                for (int ni = 0; ni < 4; ++ni) {
                    mma_tf32(acc[mi][ni], Ah[mi], Bh[ni]);
                    mma_tf32(acc[mi][ni], Al[mi], Bh[ni]);
                    mma_tf32(acc[mi][ni], Ah[mi], Bl[ni]);
                }
        }

        // split-store next slab into the other buffer
        if (s + 1 < NSLAB) {
            const int nb = buf ^ 1;
            AS(nb, am0, ak0k + 0) = split_tf32(ra0.x);
            AS(nb, am0, ak0k + 1) = split_tf32(ra0.y);
            AS(nb, am0, ak0k + 2) = split_tf32(ra0.z);
            AS(nb, am0, ak0k + 3) = split_tf32(ra0.w);
            AS(nb, am1, ak1k + 0) = split_tf32(ra1.x);
            AS(nb, am1, ak1k + 1) = split_tf32(ra1.y);
            AS(nb, am1, ak1k + 2) = split_tf32(ra1.z);
            AS(nb, am1, ak1k + 3) = split_tf32(ra1.w);
            WS(nb, wm, wk + 0) = split_tf32(rw0.x);
            WS(nb, wm, wk + 1) = split_tf32(rw0.y);
            WS(nb, wm, wk + 2) = split_tf32(rw0.z);
            WS(nb, wm, wk + 3) = split_tf32(rw0.w);
        }
        __syncthreads();
    }

    // Epilogue. C-frag mapping: c0,c1 -> row gid, cols 2*tig,2*tig+1 ; c2,c3 -> row gid+8.
#pragma unroll
    for (int mi = 0; mi < 2; ++mi) {
#pragma unroll
        for (int ci = 0; ci < 2; ++ci) {
            const int row = n0 + warpM * 32 + mi * 16 + gid + ci * 8;
#pragma unroll
            for (int ni = 0; ni < 4; ++ni) {
#pragma unroll
                for (int cj = 0; cj < 2; ++cj) {
                    const int col = o0 + warpN * 32 + ni * 8 + tig * 2 + cj;
                    const float v = acc[mi][ni][ci * 2 + cj] + bias[col];
                    if (MODE == 0) {
                        const int bb = row / T_;
                        const int t  = row - bb * T_;
                        const int part = col / C_;          // 0=q, 1=k, 2=v
                        const int c0 = col - part * C_;
                        const int h = c0 / HD_;
                        const int d = c0 - h * HD_;
                        float* dst = (part == 0) ? g_q : ((part == 1) ? g_k : g_v);
                        dst[(((size_t)bb * NH_ + h) * T_ + t) * HD_ + d] = v;
                    } else {
                        out[(size_t)row * C_ + col] = v;
                    }
                }
            }
        }
    }
#undef AS
#undef WS
}

// ---------------------------------------------------------------------------
// Causal flash attention: 1 thread = 1 query row. Online softmax over 16-key
// shared-memory chunks. grid = (B*NH, T/128), block = 128.
// ---------------------------------------------------------------------------
__global__ __launch_bounds__(128) void attn_kernel()
{
    const int bh = blockIdx.x;            // 0..B*NH-1
    const int q0 = blockIdx.y * 128;
    const int tid = threadIdx.x;
    const int qi = q0 + tid;              // this thread's query index

    __shared__ float Ks[16][HD_];
    __shared__ float Vs[16][HD_];

    const float* qp = g_q + ((size_t)bh * T_ + qi) * HD_;
    float qreg[HD_];
#pragma unroll
    for (int d = 0; d < HD_; ++d) qreg[d] = qp[d];

    float acc[HD_];
#pragma unroll
    for (int d = 0; d < HD_; ++d) acc[d] = 0.f;

    float m = -1e30f;
    float l = 0.f;
    const float scale = 0.14433756729740643f;  // 1/sqrt(48)

    const int kend = q0 + 128;

    for (int kc = 0; kc < kend; kc += 16) {
        const float4* kg = (const float4*)(g_k + ((size_t)bh * T_ + kc) * HD_);
        const float4* vg = (const float4*)(g_v + ((size_t)bh * T_ + kc) * HD_);
        float4* ks4 = (float4*)&Ks[0][0];
        float4* vs4 = (float4*)&Vs[0][0];
        __syncthreads();
        for (int i = tid; i < 192; i += 128) {
            ks4[i] = kg[i];
            vs4[i] = vg[i];
        }
        __syncthreads();

        if (kc <= qi) {
            float s[16];
            float mc = -1e30f;
#pragma unroll
            for (int j = 0; j < 16; ++j) {
                float dot = 0.f;
#pragma unroll
                for (int d = 0; d < HD_; ++d)
                    dot = fmaf(qreg[d], Ks[j][d], dot);
                s[j] = (kc + j <= qi) ? dot * scale : -1e30f;
                mc = fmaxf(mc, s[j]);
            }
            const float newm = fmaxf(m, mc);
            const float f = __expf(m - newm);
            l *= f;
#pragma unroll
            for (int d = 0; d < HD_; ++d) acc[d] *= f;
#pragma unroll
            for (int j = 0; j < 16; ++j) {
                const float p = __expf(s[j] - newm);
                l += p;
#pragma unroll
                for (int d = 0; d < HD_; ++d)
                    acc[d] = fmaf(p, Vs[j][d], acc[d]);
            }
            m = newm;
        }
    }

    const float inv = 1.f / l;
    const int bb = bh / NH_;
    const int h  = bh - bb * NH_;
    float* op = g_att + ((size_t)bb * T_ + qi) * C_ + h * HD_;
#pragma unroll
    for (int d = 0; d < HD_; ++d) op[d] = acc[d] * inv;
}

// ---------------------------------------------------------------------------
extern "C" void kernel_launch(void* const* d_in, const int* in_sizes, int n_in,
                              void* d_out, int out_size)
{
    const float* x      = (const float*)d_in[0];  // [B,T,C]
    const float* attn_w = (const float*)d_in[1];  // [3C, C]
    const float* attn_b = (const float*)d_in[2];  // [3C]
    const float* proj_w = (const float*)d_in[3];  // [C, C]
    const float* proj_b = (const float*)d_in[4];  // [C]
    float* out = (float*)d_out;                   // [B,T,C]

    const int smem_bytes = SMEM_U2 * (int)sizeof(uint2);  // 61440

    cudaFuncSetAttribute(tgemm_kernel<0>,
                         cudaFuncAttributeMaxDynamicSharedMemorySize, smem_bytes);
    cudaFuncSetAttribute(tgemm_kernel<1>,
                         cudaFuncAttributeMaxDynamicSharedMemorySize, smem_bytes);

    // Stage 1: QKV projection + head-major scatter
    {
        dim3 grid(B_ * T_ / BM, (3 * C_) / BN);   // (512, 18)
        tgemm_kernel<0><<<grid, 256, smem_bytes>>>(x, attn_w, attn_b, nullptr);
    }
    // Stage 2: causal attention
    {
        dim3 grid(B_ * NH_, T_ / 128);            // (2048, 2)
        attn_kernel<<<grid, 128>>>();
    }
    // Stage 3: output projection
    {
        dim3 grid(B_ * T_ / BM, C_ / BN);         // (512, 6)
        tgemm_kernel<1><<<grid, 256, smem_bytes>>>(nullptr, proj_w, proj_b, out);
    }
}

// round 5
// speedup vs baseline: 1.4296x; 1.4296x over previous
#include <cuda_runtime.h>
#include <cuda_bf16.h>
#include <cstdint>

// Problem constants
#define B_   256
#define T_   256
#define C_   384
#define NH_  8
#define HD_  48
#define KDIM 384

// ---------------------------------------------------------------------------
// Global scratch (static __device__ arrays — no allocation APIs allowed)
// ---------------------------------------------------------------------------
__device__ float g_q[B_ * NH_ * T_ * HD_];    // [B, NH, T, HD]
__device__ float g_k[B_ * NH_ * T_ * HD_];
__device__ float g_v[B_ * NH_ * T_ * HD_];

__device__ __nv_bfloat16 g_xh[B_ * T_ * C_];  // x split hi/lo
__device__ __nv_bfloat16 g_xl[B_ * T_ * C_];
__device__ __nv_bfloat16 g_awh[3 * C_ * C_];  // attn_w split
__device__ __nv_bfloat16 g_awl[3 * C_ * C_];
__device__ __nv_bfloat16 g_pwh[C_ * C_];      // proj_w split
__device__ __nv_bfloat16 g_pwl[C_ * C_];
__device__ __nv_bfloat16 g_ath[B_ * T_ * C_]; // attention output split
__device__ __nv_bfloat16 g_atl[B_ * T_ * C_];

// ---------------------------------------------------------------------------
// PTX helpers
// ---------------------------------------------------------------------------
__device__ __forceinline__ uint32_t smem_to_u32(const void* p) {
    uint32_t a;
    asm("{ .reg .u64 t; cvta.to.shared.u64 t, %1; cvt.u32.u64 %0, t; }"
        : "=r"(a) : "l"(p));
    return a;
}

#define CP_ASYNC16(dst, src) \
    asm volatile("cp.async.cg.shared.global [%0], [%1], 16;" \
                 :: "r"(dst), "l"(src))
#define CP_COMMIT() asm volatile("cp.async.commit_group;" ::: "memory")
#define CP_WAIT1()  asm volatile("cp.async.wait_group 1;" ::: "memory")
#define CP_WAIT0()  asm volatile("cp.async.wait_group 0;" ::: "memory")

__device__ __forceinline__ void ldm_x4(uint32_t r[4], uint32_t addr) {
    asm volatile("ldmatrix.sync.aligned.m8n8.x4.shared.b16 {%0,%1,%2,%3}, [%4];"
                 : "=r"(r[0]), "=r"(r[1]), "=r"(r[2]), "=r"(r[3]) : "r"(addr));
}

__device__ __forceinline__ void mma_bf16(float c[4], const uint32_t a[4], const uint32_t b[2]) {
    asm volatile(
        "mma.sync.aligned.m16n8k16.row.col.f32.bf16.bf16.f32 "
        "{%0,%1,%2,%3}, {%4,%5,%6,%7}, {%8,%9}, {%0,%1,%2,%3};"
        : "+f"(c[0]), "+f"(c[1]), "+f"(c[2]), "+f"(c[3])
        : "r"(a[0]), "r"(a[1]), "r"(a[2]), "r"(a[3]),
          "r"(b[0]), "r"(b[1]));
}

// ---------------------------------------------------------------------------
// Split kernels: fp32 -> bf16 hi + bf16 lo (lo = bf16(a - hi))
// TARGET: 0 -> (g_xh,g_xl), 1 -> (g_awh,g_awl), 2 -> (g_pwh,g_pwl)
// ---------------------------------------------------------------------------
template <int TARGET>
__global__ void split_kernel(const float* __restrict__ src, int n4)
{
    __nv_bfloat16* hi = (TARGET == 0) ? g_xh : (TARGET == 1) ? g_awh : g_pwh;
    __nv_bfloat16* lo = (TARGET == 0) ? g_xl : (TARGET == 1) ? g_awl : g_pwl;
    int i = blockIdx.x * blockDim.x + threadIdx.x;
    const int stride = gridDim.x * blockDim.x;
    for (; i < n4; i += stride) {
        const float4 v = ((const float4*)src)[i];
        __nv_bfloat16 h0 = __float2bfloat16(v.x);
        __nv_bfloat16 h1 = __float2bfloat16(v.y);
        __nv_bfloat16 h2 = __float2bfloat16(v.z);
        __nv_bfloat16 h3 = __float2bfloat16(v.w);
        __nv_bfloat16 l0 = __float2bfloat16(v.x - __bfloat162float(h0));
        __nv_bfloat16 l1 = __float2bfloat16(v.y - __bfloat162float(h1));
        __nv_bfloat16 l2 = __float2bfloat16(v.z - __bfloat162float(h2));
        __nv_bfloat16 l3 = __float2bfloat16(v.w - __bfloat162float(h3));
        ((__nv_bfloat162*)hi)[2 * i + 0] = __nv_bfloat162{h0, h1};
        ((__nv_bfloat162*)hi)[2 * i + 1] = __nv_bfloat162{h2, h3};
        ((__nv_bfloat162*)lo)[2 * i + 0] = __nv_bfloat162{l0, l1};
        ((__nv_bfloat162*)lo)[2 * i + 1] = __nv_bfloat162{l2, l3};
    }
}

// ---------------------------------------------------------------------------
// bf16 3-term compensated GEMM via mma.sync m16n8k16 + ldmatrix + cp.async.
//   C[n,o] = sum_k A[n,k]*W[o,k] + bias[o]
// Block tile 128(M) x 64(N), BK=32, 256 threads = 8 warps, warp tile 32x32.
// SMEM rows padded to 40 bf16 (80B) -> conflict-free ldmatrix.
// 2-stage cp.async pipeline. Inputs are pre-split bf16 hi/lo (device globals).
// MODE 0: QKV (A=g_xh/g_xl, W=g_awh/g_awl; scatter epilogue to g_q/g_k/g_v)
// MODE 1: proj (A=g_ath/g_atl, W=g_pwh/g_pwl; linear epilogue + bias)
// ---------------------------------------------------------------------------
#define BM 128
#define BN 64
#define BK 32
#define NS (KDIM / BK)            // 12 stages
#define RSB 80                    // smem row stride in bytes (40 bf16)
#define AH_OFF 0
#define AL_OFF (BM * RSB)                 // 10240
#define BH_OFF (2 * BM * RSB)             // 20480
#define BL_OFF (2 * BM * RSB + BN * RSB)  // 25600
#define STAGE_B (2 * BM * RSB + 2 * BN * RSB)   // 30720
#define GEMM_SMEM (2 * STAGE_B)                 // 61440

template <int MODE>
__global__ __launch_bounds__(256) void tc_gemm_kernel(
    const float* __restrict__ bias,
    float* __restrict__ out)
{
    extern __shared__ char smem[];
    const uint32_t sbase = smem_to_u32(smem);

    const int tid  = threadIdx.x;
    const int wid  = tid >> 5;
    const int lane = tid & 31;
    const int gid  = lane >> 2;
    const int tig  = lane & 3;

    const int warpM = wid & 3;    // 4 warps in M -> 128 rows
    const int warpN = wid >> 2;   // 2 warps in N -> 64 cols

    const int n0 = blockIdx.x * BM;
    const int o0 = blockIdx.y * BN;

    const __nv_bfloat16* Ah = (MODE == 0) ? g_xh : g_ath;
    const __nv_bfloat16* Al = (MODE == 0) ? g_xl : g_atl;
    const __nv_bfloat16* Wh = (MODE == 0) ? g_awh : g_pwh;
    const __nv_bfloat16* Wl = (MODE == 0) ? g_awl : g_pwl;

    // cp.async mapping. A: 128 rows x 64B = 512 chunks -> 2/thread.
    //                   W:  64 rows x 64B = 256 chunks -> 1/thread.
    const int ar0 = tid >> 1;               // chunk i = tid*? -> use i = tid, tid+256
    // chunk i: row = i>>2, ch = i&3
    const int a_row0 = (tid) >> 2,        a_ch0 = (tid) & 3;
    const int a_row1 = (tid + 256) >> 2,  a_ch1 = (tid + 256) & 3;
    const int b_row  = tid >> 2,          b_ch  = tid & 3;
    (void)ar0;

    const __nv_bfloat16* gAh0 = Ah + (size_t)(n0 + a_row0) * KDIM + a_ch0 * 8;
    const __nv_bfloat16* gAh1 = Ah + (size_t)(n0 + a_row1) * KDIM + a_ch1 * 8;
    const __nv_bfloat16* gAl0 = Al + (size_t)(n0 + a_row0) * KDIM + a_ch0 * 8;
    const __nv_bfloat16* gAl1 = Al + (size_t)(n0 + a_row1) * KDIM + a_ch1 * 8;
    const __nv_bfloat16* gWh  = Wh + (size_t)(o0 + b_row) * KDIM + b_ch * 8;
    const __nv_bfloat16* gWl  = Wl + (size_t)(o0 + b_row) * KDIM + b_ch * 8;

    const uint32_t sA0 = (uint32_t)(a_row0 * RSB + a_ch0 * 16);
    const uint32_t sA1 = (uint32_t)(a_row1 * RSB + a_ch1 * 16);
    const uint32_t sB  = (uint32_t)(b_row * RSB + b_ch * 16);

    // ldmatrix per-thread offsets (byte offsets within a tile)
    // A (16x16 per mi): row = warpM*32 + mi*16 + (lane&15), col = (lane>>4)*8
    uint32_t a_off[2];
#pragma unroll
    for (int mi = 0; mi < 2; ++mi)
        a_off[mi] = (uint32_t)((warpM * 32 + mi * 16 + (lane & 15)) * RSB
                               + ((lane >> 4) * 8) * 2);
    // B (16 n x 16 k per tp): n = warpN*32 + tp*16 + ((lane>>4)&1)*8 + (lane&7)
    //                          col = ((lane>>3)&1)*8
    uint32_t b_off[2];
#pragma unroll
    for (int tp = 0; tp < 2; ++tp)
        b_off[tp] = (uint32_t)((warpN * 32 + tp * 16 + ((lane >> 4) & 1) * 8 + (lane & 7)) * RSB
                               + (((lane >> 3) & 1) * 8) * 2);

    float acc[2][4][4];
#pragma unroll
    for (int mi = 0; mi < 2; ++mi)
#pragma unroll
        for (int ni = 0; ni < 4; ++ni)
#pragma unroll
            for (int c = 0; c < 4; ++c) acc[mi][ni][c] = 0.f;

    // ---- prologue: stage 0
    {
        const uint32_t st = sbase;
        CP_ASYNC16(st + AH_OFF + sA0, gAh0);
        CP_ASYNC16(st + AH_OFF + sA1, gAh1);
        CP_ASYNC16(st + AL_OFF + sA0, gAl0);
        CP_ASYNC16(st + AL_OFF + sA1, gAl1);
        CP_ASYNC16(st + BH_OFF + sB,  gWh);
        CP_ASYNC16(st + BL_OFF + sB,  gWl);
        CP_COMMIT();
    }

    for (int s = 0; s < NS; ++s) {
        if (s + 1 < NS) {
            const uint32_t st = sbase + ((s + 1) & 1) * STAGE_B;
            const int k0 = (s + 1) * BK;
            CP_ASYNC16(st + AH_OFF + sA0, gAh0 + k0);
            CP_ASYNC16(st + AH_OFF + sA1, gAh1 + k0);
            CP_ASYNC16(st + AL_OFF + sA0, gAl0 + k0);
            CP_ASYNC16(st + AL_OFF + sA1, gAl1 + k0);
            CP_ASYNC16(st + BH_OFF + sB,  gWh + k0);
            CP_ASYNC16(st + BL_OFF + sB,  gWl + k0);
            CP_COMMIT();
            CP_WAIT1();
        } else {
            CP_WAIT0();
        }
        __syncthreads();

        const uint32_t st = sbase + (s & 1) * STAGE_B;
#pragma unroll
        for (int kk = 0; kk < 2; ++kk) {           // two k16 steps
            const uint32_t kb = (uint32_t)(kk * 32); // 16 bf16 = 32 bytes
            uint32_t Af[2][4], Alf[2][4];
#pragma unroll
            for (int mi = 0; mi < 2; ++mi) {
                ldm_x4(Af[mi],  st + AH_OFF + a_off[mi] + kb);
                ldm_x4(Alf[mi], st + AL_OFF + a_off[mi] + kb);
            }
            uint32_t Bf[2][4], Blf[2][4];
#pragma unroll
            for (int tp = 0; tp < 2; ++tp) {
                ldm_x4(Bf[tp],  st + BH_OFF + b_off[tp] + kb);
                ldm_x4(Blf[tp], st + BL_OFF + b_off[tp] + kb);
            }
#pragma unroll
            for (int mi = 0; mi < 2; ++mi)
#pragma unroll
                for (int ni = 0; ni < 4; ++ni) {
                    const uint32_t* bh = &Bf[ni >> 1][(ni & 1) * 2];
                    const uint32_t* bl = &Blf[ni >> 1][(ni & 1) * 2];
                    mma_bf16(acc[mi][ni], Af[mi],  bh);
                    mma_bf16(acc[mi][ni], Alf[mi], bh);
                    mma_bf16(acc[mi][ni], Af[mi],  bl);
                }
        }
        __syncthreads();
    }

    // Epilogue. C-frag: c0,c1 -> row gid, cols 2*tig,2*tig+1 ; c2,c3 -> row gid+8.
#pragma unroll
    for (int mi = 0; mi < 2; ++mi) {
#pragma unroll
        for (int ci = 0; ci < 2; ++ci) {
            const int row = n0 + warpM * 32 + mi * 16 + gid + ci * 8;
            const int bb = row / T_;
            const int t  = row - bb * T_;
#pragma unroll
            for (int ni = 0; ni < 4; ++ni) {
#pragma unroll
                for (int cj = 0; cj < 2; ++cj) {
                    const int col = o0 + warpN * 32 + ni * 8 + tig * 2 + cj;
                    const float v = acc[mi][ni][ci * 2 + cj] + bias[col];
                    if (MODE == 0) {
                        const int part = col / C_;          // 0=q, 1=k, 2=v
                        const int c0 = col - part * C_;
                        const int h = c0 / HD_;
                        const int dd = c0 - h * HD_;
                        float* dst = (part == 0) ? g_q : ((part == 1) ? g_k : g_v);
                        dst[(((size_t)bb * NH_ + h) * T_ + t) * HD_ + dd] = v;
                    } else {
                        out[(size_t)row * C_ + col] = v;
                    }
                }
            }
        }
    }
}

// ---------------------------------------------------------------------------
// Causal flash attention: 1 thread = 1 query row. Online softmax over 16-key
// shared-memory chunks. Emits bf16 hi/lo directly for the proj GEMM.
// grid = (B*NH, T/128), block = 128.
// ---------------------------------------------------------------------------
__global__ __launch_bounds__(128) void attn_kernel()
{
    const int bh = blockIdx.x;
    const int q0 = blockIdx.y * 128;
    const int tid = threadIdx.x;
    const int qi = q0 + tid;

    __shared__ float Ks[16][HD_];
    __shared__ float Vs[16][HD_];

    const float* qp = g_q + ((size_t)bh * T_ + qi) * HD_;
    float qreg[HD_];
#pragma unroll
    for (int d = 0; d < HD_; ++d) qreg[d] = qp[d];

    float acc[HD_];
#pragma unroll
    for (int d = 0; d < HD_; ++d) acc[d] = 0.f;

    float m = -1e30f;
    float l = 0.f;
    const float scale = 0.14433756729740643f;  // 1/sqrt(48)

    const int kend = q0 + 128;

    for (int kc = 0; kc < kend; kc += 16) {
        const float4* kg = (const float4*)(g_k + ((size_t)bh * T_ + kc) * HD_);
        const float4* vg = (const float4*)(g_v + ((size_t)bh * T_ + kc) * HD_);
        float4* ks4 = (float4*)&Ks[0][0];
        float4* vs4 = (float4*)&Vs[0][0];
        __syncthreads();
        for (int i = tid; i < 192; i += 128) {
            ks4[i] = kg[i];
            vs4[i] = vg[i];
        }
        __syncthreads();

        if (kc <= qi) {
            float s[16];
            float mc = -1e30f;
#pragma unroll
            for (int j = 0; j < 16; ++j) {
                float dot = 0.f;
#pragma unroll
                for (int d = 0; d < HD_; ++d)
                    dot = fmaf(qreg[d], Ks[j][d], dot);
                s[j] = (kc + j <= qi) ? dot * scale : -1e30f;
                mc = fmaxf(mc, s[j]);
            }
            const float newm = fmaxf(m, mc);
            const float f = __expf(m - newm);
            l *= f;
#pragma unroll
            for (int d = 0; d < HD_; ++d) acc[d] *= f;
#pragma unroll
            for (int j = 0; j < 16; ++j) {
                const float p = __expf(s[j] - newm);
                l += p;
#pragma unroll
                for (int d = 0; d < HD_; ++d)
                    acc[d] = fmaf(p, Vs[j][d], acc[d]);
            }
            m = newm;
        }
    }

    const float inv = 1.f / l;
    const int bb = bh / NH_;
    const int h  = bh - bb * NH_;
    const size_t base = ((size_t)bb * T_ + qi) * C_ + h * HD_;
#pragma unroll
    for (int d = 0; d < HD_; ++d) {
        const float o = acc[d] * inv;
        const __nv_bfloat16 hi = __float2bfloat16(o);
        g_ath[base + d] = hi;
        g_atl[base + d] = __float2bfloat16(o - __bfloat162float(hi));
    }
}

// ---------------------------------------------------------------------------
extern "C" void kernel_launch(void* const* d_in, const int* in_sizes, int n_in,
                              void* d_out, int out_size)
{
    const float* x      = (const float*)d_in[0];  // [B,T,C]
    const float* attn_b = (const float*)d_in[2];  // [3C]
    const float* attn_w = (const float*)d_in[1];  // [3C, C]
    const float* proj_w = (const float*)d_in[3];  // [C, C]
    const float* proj_b = (const float*)d_in[4];  // [C]
    float* out = (float*)d_out;                   // [B,T,C]

    cudaFuncSetAttribute(tc_gemm_kernel<0>,
                         cudaFuncAttributeMaxDynamicSharedMemorySize, GEMM_SMEM);
    cudaFuncSetAttribute(tc_gemm_kernel<1>,
                         cudaFuncAttributeMaxDynamicSharedMemorySize, GEMM_SMEM);

    // Stage 0: fp32 -> bf16 hi/lo splits
    split_kernel<0><<<2048, 256>>>(x,      B_ * T_ * C_ / 4);
    split_kernel<1><<<432,  256>>>(attn_w, 3 * C_ * C_ / 4);
    split_kernel<2><<<144,  256>>>(proj_w, C_ * C_ / 4);

    // Stage 1: QKV projection + head-major scatter
    {
        dim3 grid(B_ * T_ / BM, (3 * C_) / BN);   // (512, 18)
        tc_gemm_kernel<0><<<grid, 256, GEMM_SMEM>>>(attn_b, nullptr);
    }
    // Stage 2: causal attention (emits bf16 hi/lo)
    {
        dim3 grid(B_ * NH_, T_ / 128);            // (2048, 2)
        attn_kernel<<<grid, 128>>>();
    }
    // Stage 3: output projection
    {
        dim3 grid(B_ * T_ / BM, C_ / BN);         // (512, 6)
        tc_gemm_kernel<1><<<grid, 256, GEMM_SMEM>>>(proj_b, out);
    }
}